// round 3
// baseline (speedup 1.0000x reference)
#include <cuda_runtime.h>
#include <cuda_bf16.h>
#include <cstdint>

// ============================================================================
// ReuploadingQuantumLayer: 10-qubit statevector sim, 4 layers.
// One warp per batch element; 1024 complex amps = 32 float2 regs/lane.
// CNOT rings are never applied to data: tracked as a compile-time GF(2)
// basis transform T; gates act on XOR-mask pairs with parity-selected coeffs.
// ============================================================================

#define FULLM 0xFFFFFFFFu
#define N_Q 10
#define N_L 4

// ---------------- compile-time GF(2) linear algebra (10x10 bit matrices) ----
struct M10 { unsigned r[10]; };

__host__ __device__ constexpr M10 midentity() {
    M10 m{{0,0,0,0,0,0,0,0,0,0}};
    for (int i = 0; i < 10; i++) m.r[i] = 1u << i;
    return m;
}
// matrix product (a*b): (a*b)x = a(b x)
__host__ __device__ constexpr M10 mmul(M10 a, M10 b) {
    M10 c{{0,0,0,0,0,0,0,0,0,0}};
    for (int i = 0; i < 10; i++) {
        unsigned v = 0;
        for (int j = 0; j < 10; j++)
            if ((a.r[i] >> j) & 1u) v ^= b.r[j];
        c.r[i] = v;
    }
    return c;
}
// CNOT(c,t) as index map b -> b ^ (bit_c(b)<<t):  row_t = e_t ^ e_c
__host__ __device__ constexpr M10 mcnot(int c, int t) {
    M10 m = midentity();
    m.r[t] ^= (1u << c);
    return m;
}
// One CNOT-ring round: psi_new[x] = psi_old[R x], R = M0*M1*...*M9
__host__ __device__ constexpr M10 rmat() {
    M10 p = mcnot(0, 1);
    for (int c = 1; c < 10; c++) p = mmul(p, mcnot(c, (c + 1) % 10));
    return p;
}
__host__ __device__ constexpr M10 rinvmat() {
    M10 p = mcnot(9, 0);
    for (int c = 8; c >= 0; c--) p = mmul(p, mcnot(c, c + 1));
    return p;
}
// Invariant: stored[p] = true[T_l p],  T_l = (R^-1)^l,  Tinv_l = R^l
__host__ __device__ constexpr M10 tmat(int l) {
    M10 t = midentity();
    for (int k = 0; k < l; k++) t = mmul(rinvmat(), t);
    return t;
}
__host__ __device__ constexpr M10 tinvmat(int l) {
    M10 t = midentity();
    for (int k = 0; k < l; k++) t = mmul(t, rmat());
    return t;
}
__host__ __device__ constexpr unsigned t_row(int l, int q) { return tmat(l).r[q]; }
__host__ __device__ constexpr unsigned tinv_col(int l, int q) {
    M10 ti = tinvmat(l);
    unsigned v = 0;
    for (int i = 0; i < 10; i++) v |= ((ti.r[i] >> q) & 1u) << i;
    return v;
}
__host__ __device__ constexpr unsigned parity_(unsigned x) {
    x ^= x >> 16; x ^= x >> 8; x ^= x >> 4; x ^= x >> 2; x ^= x >> 1;
    return x & 1u;
}
// bitmap over r in [0,32): bit r = parity(r & rml)
__host__ __device__ constexpr unsigned blow_map(unsigned rml) {
    unsigned m = 0;
    for (unsigned r2 = 0; r2 < 32; r2++) m |= parity_(r2 & rml) << r2;
    return m;
}

// ---------------- weight-derived trig table (batch independent) -------------
__device__ float4 g_wtab[40];   // per gate g=l*10+q: (cos w1/2, sin w1/2, cos w0/2, sin w0/2)

__global__ void prep_kernel(const float* __restrict__ w) {
    int g = threadIdx.x;
    if (g < 40) {
        float w0 = w[2 * g + 0];
        float w1 = w[2 * g + 1];
        float4 t;
        t.x = cosf(0.5f * w1);
        t.y = sinf(0.5f * w1);
        t.z = cosf(0.5f * w0);
        t.w = sinf(0.5f * w0);
        g_wtab[g] = t;
    }
}

// ---------------- device helpers --------------------------------------------
__device__ __forceinline__ float2 shx2(float2 v, int m) {
    float2 o;
    o.x = __shfl_xor_sync(FULLM, v.x, m);
    o.y = __shfl_xor_sync(FULLM, v.y, m);
    return o;
}
// complex: co*a + cp*b
__device__ __forceinline__ float2 cfma2(float2 co, float2 a, float2 cp, float2 b) {
    float2 r;
    r.x = fmaf(co.x, a.x, fmaf(-co.y, a.y, fmaf(cp.x, b.x, -cp.y * b.y)));
    r.y = fmaf(co.x, a.y, fmaf( co.y, a.x, fmaf(cp.x, b.y,  cp.y * b.x)));
    return r;
}

// ---------------- one gate (fully unrolled, masks are immediates) ------------
template <int G>
__device__ __forceinline__ void apply_gate(float2 (&amp)[32], int lane,
                                           float2 cs0, float2 cs1) {
    constexpr unsigned rm    = t_row(G / 10, G % 10);    // row q of T
    constexpr unsigned v     = tinv_col(G / 10, G % 10); // partner XOR mask
    constexpr unsigned vlow  = v & 31u,  vhigh = v >> 5;
    constexpr unsigned rml   = rm & 31u, rmh   = rm >> 5;
    constexpr unsigned BLOW  = blow_map(rml);

    // angles: owner lane computed (ca, sa) = (cos a/2, sin a/2)
    float ca = __shfl_sync(FULLM, (G < 32) ? cs0.x : cs1.x, G & 31);
    float sa = __shfl_sync(FULLM, (G < 32) ? cs0.y : cs1.y, G & 31);

    float4 wt = g_wtab[G];
    float cw = wt.x, sw = wt.y, cph = wt.z, sph = wt.w;
    float A = cw * ca, B = sw * sa, C = sw * ca, D = cw * sa;
    // U = [[alpha, -conj(beta)], [beta, conj(alpha)]]
    float2 al  = make_float2((A - B) * cph, -(A + B) * sph);
    float2 be  = make_float2((C + D) * cph,  (D - C) * sph);
    float2 nbc = make_float2(-be.x, be.y);   // -conj(beta)
    float2 ac  = make_float2(al.x, -al.y);   //  conj(alpha)

    // bq(p) = blane ^ blow(r); element with bq=0 is s0 (coeffs al,nbc),
    // element with bq=1 is s1 (coeffs ac,be).
    bool blane = (__popc(lane & (int)rmh) & 1) != 0;
    float2 co0 = blane ? ac : al;   // coeffs for blow(r)==0
    float2 cp0 = blane ? be : nbc;
    float2 co1 = blane ? al : ac;   // coeffs for blow(r)==1
    float2 cp1 = blane ? nbc : be;

    if (vhigh == 0u) {
        // pure in-register pairing; representative: blow(r)==0
        #pragma unroll
        for (int r = 0; r < 32; r++) {
            if (((BLOW >> r) & 1u) == 0u) {
                const int rb = r ^ (int)vlow;
                float2 a0 = amp[r], a1 = amp[rb];
                amp[r]  = cfma2(co0, a0, cp0, a1);
                amp[rb] = cfma2(co1, a1, cp1, a0);
            }
        }
    } else if (vlow == 0u) {
        // pure cross-lane: partner value at same register index
        #pragma unroll
        for (int r = 0; r < 32; r++) {
            float2 p  = shx2(amp[r], (int)vhigh);
            float2 a0 = amp[r];
            amp[r] = (((BLOW >> r) & 1u) == 0u) ? cfma2(co0, a0, cp0, p)
                                                : cfma2(co1, a0, cp1, p);
        }
    } else {
        // cross-lane + cross-register: handle reg-pairs together so both
        // shuffles read pre-update values (lockstep with partner lane)
        constexpr unsigned hb = vlow & (0u - vlow);
        #pragma unroll
        for (int r = 0; r < 32; r++) {
            if ((r & (int)hb) == 0) {
                const int rb = r ^ (int)vlow;
                float2 pA = shx2(amp[rb], (int)vhigh); // partner for amp[r]
                float2 pB = shx2(amp[r],  (int)vhigh); // partner for amp[rb]
                float2 a0 = amp[r], a1 = amp[rb];
                amp[r]  = (((BLOW >> r ) & 1u) == 0u) ? cfma2(co0, a0, cp0, pA)
                                                      : cfma2(co1, a0, cp1, pA);
                amp[rb] = (((BLOW >> rb) & 1u) == 0u) ? cfma2(co0, a1, cp0, pB)
                                                      : cfma2(co1, a1, cp1, pB);
            }
        }
    }
}

template <int G>
struct GLoop {
    static __device__ __forceinline__ void run(float2 (&amp)[32], int lane,
                                               float2 cs0, float2 cs1) {
        apply_gate<G>(amp, lane, cs0, cs1);
        GLoop<G + 1>::run(amp, lane, cs0, cs1);
    }
};
template <>
struct GLoop<40> {
    static __device__ __forceinline__ void run(float2 (&)[32], int, float2, float2) {}
};

// ---------------- measurement: <Z_q> with final transform T_4 ----------------
template <int Q>
struct MLoop {
    static __device__ __forceinline__ void run(const float (&pr)[32], int lane,
                                               float* __restrict__ outp) {
        constexpr unsigned fm  = t_row(4, Q);
        constexpr unsigned rml = fm & 31u, rmh = fm >> 5;
        constexpr unsigned BL  = blow_map(rml);
        float s = 0.f;
        #pragma unroll
        for (int r = 0; r < 32; r++)
            s += (((BL >> r) & 1u) ? -pr[r] : pr[r]);
        if (__popc(lane & (int)rmh) & 1) s = -s;
        #pragma unroll
        for (int off = 16; off; off >>= 1)
            s += __shfl_xor_sync(FULLM, s, off);
        if (lane == 0) outp[Q] = s;
        MLoop<Q + 1>::run(pr, lane, outp);
    }
};
template <>
struct MLoop<10> {
    static __device__ __forceinline__ void run(const float (&)[32], int, float*) {}
};

// ---------------- main kernel ------------------------------------------------
__global__ void __launch_bounds__(256, 2)
qsim_kernel(const float* __restrict__ x, float* __restrict__ out, int B) {
    const int lane = threadIdx.x & 31;
    const int b = blockIdx.x * (blockDim.x >> 5) + (threadIdx.x >> 5);
    if (b >= B) return;

    const float* xb = x + (size_t)b * 40;

    // data angles: a = atan(x)*pi ; owner lane L holds (cos a/2, sin a/2)
    // for gate L (cs0) and gate L+32 (cs1, lanes 0..7)
    const float PI_F = 3.14159265358979f;
    float a0 = atanf(xb[lane]) * PI_F;
    float2 cs0;
    sincosf(0.5f * a0, &cs0.y, &cs0.x);
    float2 cs1 = make_float2(1.f, 0.f);
    if (lane < 8) {
        float a1 = atanf(xb[32 + lane]) * PI_F;
        sincosf(0.5f * a1, &cs1.y, &cs1.x);
    }

    // |0...0>
    float2 amp[32];
    #pragma unroll
    for (int r = 0; r < 32; r++) amp[r] = make_float2(0.f, 0.f);
    if (lane == 0) amp[0].x = 1.f;

    GLoop<0>::run(amp, lane, cs0, cs1);

    float pr[32];
    #pragma unroll
    for (int r = 0; r < 32; r++)
        pr[r] = fmaf(amp[r].x, amp[r].x, amp[r].y * amp[r].y);

    MLoop<0>::run(pr, lane, out + (size_t)b * 10);
}

// ---------------- launch -----------------------------------------------------
extern "C" void kernel_launch(void* const* d_in, const int* in_sizes, int n_in,
                              void* d_out, int out_size) {
    const float* x = (const float*)d_in[0];   // [B, 40] fp32
    const float* w = (const float*)d_in[1];   // [4, 10, 2] fp32
    float* out = (float*)d_out;               // [B, 10] fp32

    int B = in_sizes[0] / 40;
    prep_kernel<<<1, 64>>>(w);
    int wpb = 256 / 32;
    int blocks = (B + wpb - 1) / wpb;
    qsim_kernel<<<blocks, 256>>>(x, out, B);
}

// round 4
// speedup vs baseline: 1.0112x; 1.0112x over previous
#include <cuda_runtime.h>
#include <cuda_bf16.h>
#include <cstdint>

// ============================================================================
// ReuploadingQuantumLayer: 10-qubit statevector sim, 4 layers, B=16384.
// One warp per batch element; 1024 complex amps = 32 float2 regs/lane.
// CNOT rings tracked as compile-time GF(2) basis transform (never applied).
// Layer 0 exploits |0..0> initial state: direct product-state construction.
// ============================================================================

#define FULLM 0xFFFFFFFFu

// ---------------- compile-time GF(2) linear algebra (10x10 bit matrices) ----
struct M10 { unsigned r[10]; };

__host__ __device__ constexpr M10 midentity() {
    M10 m{{0,0,0,0,0,0,0,0,0,0}};
    for (int i = 0; i < 10; i++) m.r[i] = 1u << i;
    return m;
}
__host__ __device__ constexpr M10 mmul(M10 a, M10 b) {
    M10 c{{0,0,0,0,0,0,0,0,0,0}};
    for (int i = 0; i < 10; i++) {
        unsigned v = 0;
        for (int j = 0; j < 10; j++)
            if ((a.r[i] >> j) & 1u) v ^= b.r[j];
        c.r[i] = v;
    }
    return c;
}
__host__ __device__ constexpr M10 mcnot(int c, int t) {
    M10 m = midentity();
    m.r[t] ^= (1u << c);
    return m;
}
__host__ __device__ constexpr M10 rmat() {
    M10 p = mcnot(0, 1);
    for (int c = 1; c < 10; c++) p = mmul(p, mcnot(c, (c + 1) % 10));
    return p;
}
__host__ __device__ constexpr M10 rinvmat() {
    M10 p = mcnot(9, 0);
    for (int c = 8; c >= 0; c--) p = mmul(p, mcnot(c, c + 1));
    return p;
}
// Invariant: stored[p] = true[T_l p],  T_l = (R^-1)^l,  Tinv_l = R^l
__host__ __device__ constexpr M10 tmat(int l) {
    M10 t = midentity();
    for (int k = 0; k < l; k++) t = mmul(rinvmat(), t);
    return t;
}
__host__ __device__ constexpr M10 tinvmat(int l) {
    M10 t = midentity();
    for (int k = 0; k < l; k++) t = mmul(t, rmat());
    return t;
}
__host__ __device__ constexpr unsigned t_row(int l, int q) { return tmat(l).r[q]; }
__host__ __device__ constexpr unsigned tinv_col(int l, int q) {
    M10 ti = tinvmat(l);
    unsigned v = 0;
    for (int i = 0; i < 10; i++) v |= ((ti.r[i] >> q) & 1u) << i;
    return v;
}
__host__ __device__ constexpr unsigned parity_(unsigned x) {
    x ^= x >> 16; x ^= x >> 8; x ^= x >> 4; x ^= x >> 2; x ^= x >> 1;
    return x & 1u;
}
__host__ __device__ constexpr unsigned blow_map(unsigned rml) {
    unsigned m = 0;
    for (unsigned r2 = 0; r2 < 32; r2++) m |= parity_(r2 & rml) << r2;
    return m;
}

// ---------------- weight-derived trig table (batch independent) -------------
__device__ float4 g_wtab[40];   // per gate: (cos w1/2, sin w1/2, cos w0/2, sin w0/2)

__global__ void prep_kernel(const float* __restrict__ w) {
    int g = threadIdx.x;
    if (g < 40) {
        float w0 = w[2 * g + 0];
        float w1 = w[2 * g + 1];
        float4 t;
        t.x = cosf(0.5f * w1);
        t.y = sinf(0.5f * w1);
        t.z = cosf(0.5f * w0);
        t.w = sinf(0.5f * w0);
        g_wtab[g] = t;
    }
}

// ---------------- device helpers --------------------------------------------
__device__ __forceinline__ float2 shx2(float2 v, int m) {
    float2 o;
    o.x = __shfl_xor_sync(FULLM, v.x, m);
    o.y = __shfl_xor_sync(FULLM, v.y, m);
    return o;
}
__device__ __forceinline__ float2 cmul(float2 a, float2 b) {
    return make_float2(fmaf(a.x, b.x, -a.y * b.y), fmaf(a.x, b.y, a.y * b.x));
}
// complex: co*a + cp*b  (8 fma-pipe ops)
__device__ __forceinline__ float2 cfma2(float2 co, float2 a, float2 cp, float2 b) {
    float2 r;
    r.x = fmaf(co.x, a.x, fmaf(-co.y, a.y, fmaf(cp.x, b.x, -cp.y * b.y)));
    r.y = fmaf(co.x, a.y, fmaf( co.y, a.x, fmaf(cp.x, b.y,  cp.y * b.x)));
    return r;
}

// compute (alpha, beta) for one gate from its angle trig + weight trig
__device__ __forceinline__ void gate_coeffs(float ca, float sa, float4 wt,
                                            float2& al, float2& be) {
    float cw = wt.x, sw = wt.y, cph = wt.z, sph = wt.w;
    float A = cw * ca, B = sw * sa, C = sw * ca, D = cw * sa;
    al = make_float2((A - B) * cph, -(A + B) * sph);
    be = make_float2((C + D) * cph,  (D - C) * sph);
}

// ---------------- one gate (fully unrolled, masks are immediates) ------------
// Coefficients for gate G live in lane G&31: set0 (G<32) or set1 (G>=32).
template <int G>
__device__ __forceinline__ void apply_gate(float2 (&amp)[32], int lane,
                                           float2 A0, float2 B0,
                                           float2 A1, float2 B1) {
    constexpr unsigned rm    = t_row(G / 10, G % 10);
    constexpr unsigned v     = tinv_col(G / 10, G % 10);
    constexpr unsigned vlow  = v & 31u,  vhigh = v >> 5;
    constexpr unsigned rml   = rm & 31u, rmh   = rm >> 5;
    constexpr unsigned BLOW  = blow_map(rml);
    constexpr int src = G & 31;

    float2 al, be;
    al.x = __shfl_sync(FULLM, (G < 32) ? A0.x : A1.x, src);
    al.y = __shfl_sync(FULLM, (G < 32) ? A0.y : A1.y, src);
    be.x = __shfl_sync(FULLM, (G < 32) ? B0.x : B1.x, src);
    be.y = __shfl_sync(FULLM, (G < 32) ? B0.y : B1.y, src);
    float2 nbc = make_float2(-be.x, be.y);   // -conj(beta)
    float2 ac  = make_float2(al.x, -al.y);   //  conj(alpha)

    bool blane = (__popc(lane & (int)rmh) & 1) != 0;
    float2 co0 = blane ? ac : al;   // coeffs when blow(r)==0
    float2 cp0 = blane ? be : nbc;
    float2 co1 = blane ? al : ac;   // coeffs when blow(r)==1
    float2 cp1 = blane ? nbc : be;

    if (vhigh == 0u) {
        #pragma unroll
        for (int r = 0; r < 32; r++) {
            if (((BLOW >> r) & 1u) == 0u) {
                const int rb = r ^ (int)vlow;
                float2 a0 = amp[r], a1 = amp[rb];
                amp[r]  = cfma2(co0, a0, cp0, a1);
                amp[rb] = cfma2(co1, a1, cp1, a0);
            }
        }
    } else if (vlow == 0u) {
        #pragma unroll
        for (int r = 0; r < 32; r++) {
            float2 p  = shx2(amp[r], (int)vhigh);
            float2 a0 = amp[r];
            amp[r] = (((BLOW >> r) & 1u) == 0u) ? cfma2(co0, a0, cp0, p)
                                                : cfma2(co1, a0, cp1, p);
        }
    } else {
        constexpr unsigned hb = vlow & (0u - vlow);
        #pragma unroll
        for (int r = 0; r < 32; r++) {
            if ((r & (int)hb) == 0) {
                const int rb = r ^ (int)vlow;
                float2 pA = shx2(amp[rb], (int)vhigh);
                float2 pB = shx2(amp[r],  (int)vhigh);
                float2 a0 = amp[r], a1 = amp[rb];
                amp[r]  = (((BLOW >> r ) & 1u) == 0u) ? cfma2(co0, a0, cp0, pA)
                                                      : cfma2(co1, a0, cp1, pA);
                amp[rb] = (((BLOW >> rb) & 1u) == 0u) ? cfma2(co0, a1, cp0, pB)
                                                      : cfma2(co1, a1, cp1, pB);
            }
        }
    }
}

template <int G>
struct GLoop {
    static __device__ __forceinline__ void run(float2 (&amp)[32], int lane,
                                               float2 A0, float2 B0,
                                               float2 A1, float2 B1) {
        apply_gate<G>(amp, lane, A0, B0, A1, B1);
        GLoop<G + 1>::run(amp, lane, A0, B0, A1, B1);
    }
};
template <>
struct GLoop<40> {
    static __device__ __forceinline__ void run(float2 (&)[32], int,
                                               float2, float2, float2, float2) {}
};

// ---------------- measurement: <Z_q> with final transform T_4 ----------------
template <int Q>
struct MLoop {
    static __device__ __forceinline__ void run(const float (&pr)[32], int lane,
                                               float* __restrict__ outp) {
        constexpr unsigned fm  = t_row(4, Q);
        constexpr unsigned rml = fm & 31u, rmh = fm >> 5;
        constexpr unsigned BL  = blow_map(rml);
        float s = 0.f;
        #pragma unroll
        for (int r = 0; r < 32; r++)
            s += (((BL >> r) & 1u) ? -pr[r] : pr[r]);
        if (__popc(lane & (int)rmh) & 1) s = -s;
        #pragma unroll
        for (int off = 16; off; off >>= 1)
            s += __shfl_xor_sync(FULLM, s, off);
        if (lane == 0) outp[Q] = s;
        MLoop<Q + 1>::run(pr, lane, outp);
    }
};
template <>
struct MLoop<10> {
    static __device__ __forceinline__ void run(const float (&)[32], int, float*) {}
};

// ---------------- main kernel ------------------------------------------------
__global__ void __launch_bounds__(128, 3)
qsim_kernel(const float* __restrict__ x, float* __restrict__ out, int B) {
    const int lane = threadIdx.x & 31;
    const int b = blockIdx.x * (blockDim.x >> 5) + (threadIdx.x >> 5);
    if (b >= B) return;

    const float* xb = x + (size_t)b * 40;
    const float PI_F = 3.14159265358979f;

    // ---- per-gate coefficients: lane g owns gate g (set0) and gate 32+g (set1)
    float ca0, sa0;
    __sincosf(0.5f * PI_F * atanf(xb[lane]), &sa0, &ca0);
    float2 A0, B0;
    gate_coeffs(ca0, sa0, g_wtab[lane], A0, B0);

    float2 A1 = make_float2(1.f, 0.f), B1 = make_float2(0.f, 0.f);
    if (lane < 8) {
        float ca1, sa1;
        __sincosf(0.5f * PI_F * atanf(xb[32 + lane]), &sa1, &ca1);
        gate_coeffs(ca1, sa1, g_wtab[32 + lane], A1, B1);
    }

    // ---- layer 0 shortcut: product state amp[p] = prod_q u_q[bit_q(p)] ----
    // lane factor: qubits 5..9 select by lane bits
    float2 Fz;
    {
        float2 u;
        u.x = __shfl_sync(FULLM, A0.x, 5); u.y = __shfl_sync(FULLM, A0.y, 5);
        float2 w;
        w.x = __shfl_sync(FULLM, B0.x, 5); w.y = __shfl_sync(FULLM, B0.y, 5);
        Fz = (lane & 1) ? w : u;
        #pragma unroll
        for (int j = 1; j < 5; j++) {
            int src = 5 + j;
            u.x = __shfl_sync(FULLM, A0.x, src); u.y = __shfl_sync(FULLM, A0.y, src);
            w.x = __shfl_sync(FULLM, B0.x, src); w.y = __shfl_sync(FULLM, B0.y, src);
            float2 sel = ((lane >> j) & 1) ? w : u;
            Fz = cmul(Fz, sel);
        }
    }

    float2 amp[32];
    amp[0] = Fz;
    // register doubling: qubits 0..4
    #pragma unroll
    for (int q = 0; q < 5; q++) {
        float2 u0, u1;
        u0.x = __shfl_sync(FULLM, A0.x, q); u0.y = __shfl_sync(FULLM, A0.y, q);
        u1.x = __shfl_sync(FULLM, B0.x, q); u1.y = __shfl_sync(FULLM, B0.y, q);
        #pragma unroll
        for (int r = 0; r < 32; r++) {
            if (r < (1 << q)) {
                float2 z = amp[r];
                amp[r | (1 << q)] = cmul(z, u1);
                amp[r]            = cmul(z, u0);
            }
        }
    }

    // ---- layers 1..3 (gates 10..39) ----
    GLoop<10>::run(amp, lane, A0, B0, A1, B1);

    // ---- probabilities + <Z_q> ----
    float pr[32];
    #pragma unroll
    for (int r = 0; r < 32; r++)
        pr[r] = fmaf(amp[r].x, amp[r].x, amp[r].y * amp[r].y);

    MLoop<0>::run(pr, lane, out + (size_t)b * 10);
}

// ---------------- launch -----------------------------------------------------
extern "C" void kernel_launch(void* const* d_in, const int* in_sizes, int n_in,
                              void* d_out, int out_size) {
    const float* x = (const float*)d_in[0];   // [B, 40] fp32
    const float* w = (const float*)d_in[1];   // [4, 10, 2] fp32
    float* out = (float*)d_out;               // [B, 10] fp32

    int B = in_sizes[0] / 40;
    prep_kernel<<<1, 64>>>(w);
    const int THREADS = 128;
    int wpb = THREADS / 32;
    int blocks = (B + wpb - 1) / wpb;
    qsim_kernel<<<blocks, THREADS>>>(x, out, B);
}

// round 6
// speedup vs baseline: 1.6720x; 1.6535x over previous
#include <cuda_runtime.h>
#include <cuda_bf16.h>
#include <cstdint>

// ============================================================================
// ReuploadingQuantumLayer: 10-qubit statevector sim, 4 layers, B=16384.
// One warp per batch element; 1024 complex amps = 32 packed f32x2 regs/lane.
// CNOT rings tracked as compile-time GF(2) basis transform (never applied).
// Layer 0 exploits |0..0>: direct product-state construction.
// Complex arithmetic via Blackwell packed fma.rn.f32x2 (PTX-only FFMA2).
// ============================================================================

#define FULLM 0xFFFFFFFFu
typedef unsigned long long u64;

// ---------------- compile-time GF(2) linear algebra (10x10 bit matrices) ----
struct M10 { unsigned r[10]; };

__host__ __device__ constexpr M10 midentity() {
    M10 m{{0,0,0,0,0,0,0,0,0,0}};
    for (int i = 0; i < 10; i++) m.r[i] = 1u << i;
    return m;
}
__host__ __device__ constexpr M10 mmul(M10 a, M10 b) {
    M10 c{{0,0,0,0,0,0,0,0,0,0}};
    for (int i = 0; i < 10; i++) {
        unsigned v = 0;
        for (int j = 0; j < 10; j++)
            if ((a.r[i] >> j) & 1u) v ^= b.r[j];
        c.r[i] = v;
    }
    return c;
}
__host__ __device__ constexpr M10 mcnot(int c, int t) {
    M10 m = midentity();
    m.r[t] ^= (1u << c);
    return m;
}
__host__ __device__ constexpr M10 rmat() {
    M10 p = mcnot(0, 1);
    for (int c = 1; c < 10; c++) p = mmul(p, mcnot(c, (c + 1) % 10));
    return p;
}
__host__ __device__ constexpr M10 rinvmat() {
    M10 p = mcnot(9, 0);
    for (int c = 8; c >= 0; c--) p = mmul(p, mcnot(c, c + 1));
    return p;
}
// Invariant: stored[p] = true[T_l p],  T_l = (R^-1)^l,  Tinv_l = R^l
__host__ __device__ constexpr M10 tmat(int l) {
    M10 t = midentity();
    for (int k = 0; k < l; k++) t = mmul(rinvmat(), t);
    return t;
}
__host__ __device__ constexpr M10 tinvmat(int l) {
    M10 t = midentity();
    for (int k = 0; k < l; k++) t = mmul(t, rmat());
    return t;
}
__host__ __device__ constexpr unsigned t_row(int l, int q) { return tmat(l).r[q]; }
__host__ __device__ constexpr unsigned tinv_col(int l, int q) {
    M10 ti = tinvmat(l);
    unsigned v = 0;
    for (int i = 0; i < 10; i++) v |= ((ti.r[i] >> q) & 1u) << i;
    return v;
}
__host__ __device__ constexpr unsigned parity_(unsigned x) {
    x ^= x >> 16; x ^= x >> 8; x ^= x >> 4; x ^= x >> 2; x ^= x >> 1;
    return x & 1u;
}
__host__ __device__ constexpr unsigned blow_map(unsigned rml) {
    unsigned m = 0;
    for (unsigned r2 = 0; r2 < 32; r2++) m |= parity_(r2 & rml) << r2;
    return m;
}

// ---------------- weight-derived trig table (batch independent) -------------
__device__ float4 g_wtab[40];   // per gate: (cos w1/2, sin w1/2, cos w0/2, sin w0/2)

__global__ void prep_kernel(const float* __restrict__ w) {
    int g = threadIdx.x;
    if (g < 40) {
        float w0 = w[2 * g + 0];
        float w1 = w[2 * g + 1];
        float4 t;
        t.x = cosf(0.5f * w1);
        t.y = sinf(0.5f * w1);
        t.z = cosf(0.5f * w0);
        t.w = sinf(0.5f * w0);
        g_wtab[g] = t;
    }
}

// ---------------- packed f32x2 primitives ------------------------------------
__device__ __forceinline__ u64 pack2(float lo, float hi) {
    u64 r;
    asm("mov.b64 %0, {%1, %2};" : "=l"(r) : "f"(lo), "f"(hi));
    return r;
}
__device__ __forceinline__ void unpack2(u64 v, float& lo, float& hi) {
    asm("mov.b64 {%0, %1}, %2;" : "=f"(lo), "=f"(hi) : "l"(v));
}
__device__ __forceinline__ u64 swp(u64 v) {   // (x,y) -> (y,x)
    float lo, hi;
    unpack2(v, lo, hi);
    return pack2(hi, lo);
}
__device__ __forceinline__ u64 fma2(u64 a, u64 b, u64 c) {
    u64 d;
    asm("fma.rn.f32x2 %0, %1, %2, %3;" : "=l"(d) : "l"(a), "l"(b), "l"(c));
    return d;
}
__device__ __forceinline__ u64 mul2(u64 a, u64 b) {
    u64 d;
    asm("mul.rn.f32x2 %0, %1, %2;" : "=l"(d) : "l"(a), "l"(b));
    return d;
}
__device__ __forceinline__ u64 shx64(u64 v, int m) {
    return __shfl_xor_sync(FULLM, v, m);
}

// packed gate coefficients (6 f32x2 vectors)
struct GC { u64 Ax, Ay, AyN, Bx, BxN, By; };

// out = U_row applied to (self, partner):  side 0 <-> bq==0,  side 1 <-> bq==1
__device__ __forceinline__ u64 upd0(const GC& g, u64 a, u64 aS, u64 b, u64 bS) {
    return fma2(g.Ax, a, fma2(g.Ay, aS, fma2(g.Bx, b, mul2(g.By, bS))));
}
__device__ __forceinline__ u64 upd1(const GC& g, u64 a, u64 aS, u64 b, u64 bS) {
    return fma2(g.Ax, a, fma2(g.AyN, aS, fma2(g.BxN, b, mul2(g.By, bS))));
}

// ---------------- one gate (fully unrolled, masks are immediates) ------------
// Coefficients for gate G live in lane G&31: set0 (G<32) or set1 (G>=32).
template <int G>
__device__ __forceinline__ void apply_gate(u64 (&amp)[32], int lane,
                                           float2 A0, float2 B0,
                                           float2 A1, float2 B1) {
    constexpr unsigned rm    = t_row(G / 10, G % 10);
    constexpr unsigned v     = tinv_col(G / 10, G % 10);
    constexpr unsigned vlow  = v & 31u,  vhigh = v >> 5;
    constexpr unsigned rml   = rm & 31u, rmh   = rm >> 5;
    constexpr unsigned BLOW  = blow_map(rml);
    constexpr int src = G & 31;

    // broadcast alpha, beta (computed by owner lane)
    float alx = __shfl_sync(FULLM, (G < 32) ? A0.x : A1.x, src);
    float aly = __shfl_sync(FULLM, (G < 32) ? A0.y : A1.y, src);
    float bex = __shfl_sync(FULLM, (G < 32) ? B0.x : B1.x, src);
    float bey = __shfl_sync(FULLM, (G < 32) ? B0.y : B1.y, src);

    // lane parity folds into coefficient signs:
    //   co0 = (alx, e*aly), cp0 = (-e*bex, bey); co1 = conj(co0), cp1 = -conj(cp0)
    bool blane = (__popc(lane & (int)rmh) & 1) != 0;
    float e  = blane ? -1.f : 1.f;
    float ey = e * aly;
    float ex = e * bex;

    GC g;
    g.Ax  = pack2(alx, alx);
    g.Ay  = pack2(-ey,  ey);
    g.AyN = pack2( ey, -ey);
    g.Bx  = pack2(-ex, -ex);
    g.BxN = pack2( ex,  ex);
    g.By  = pack2(-bey, bey);

    if (vhigh == 0u) {
        // pure in-register pairing; representative: blow(r)==0
        #pragma unroll
        for (int r = 0; r < 32; r++) {
            if (((BLOW >> r) & 1u) == 0u) {
                const int rb = r ^ (int)vlow;
                u64 a0 = amp[r], a1 = amp[rb];
                u64 a0S = swp(a0), a1S = swp(a1);
                amp[r]  = upd0(g, a0, a0S, a1, a1S);
                amp[rb] = upd1(g, a1, a1S, a0, a0S);
            }
        }
    } else if (vlow == 0u) {
        // pure cross-lane: partner at same register index
        #pragma unroll
        for (int r = 0; r < 32; r++) {
            u64 p  = shx64(amp[r], (int)vhigh);
            u64 a  = amp[r];
            u64 aS = swp(a), pS = swp(p);
            amp[r] = (((BLOW >> r) & 1u) == 0u) ? upd0(g, a, aS, p, pS)
                                                : upd1(g, a, aS, p, pS);
        }
    } else {
        // cross-lane + cross-register: reg-pairs handled together so both
        // shuffles read pre-update values (lockstep with partner lane)
        constexpr unsigned hb = vlow & (0u - vlow);
        #pragma unroll
        for (int r = 0; r < 32; r++) {
            if ((r & (int)hb) == 0) {
                const int rb = r ^ (int)vlow;
                u64 pA = shx64(amp[rb], (int)vhigh);   // partner for amp[r]
                u64 pB = shx64(amp[r],  (int)vhigh);   // partner for amp[rb]
                u64 a0 = amp[r], a1 = amp[rb];
                u64 a0S = swp(a0), a1S = swp(a1);
                u64 pAS = swp(pA), pBS = swp(pB);
                amp[r]  = (((BLOW >> r ) & 1u) == 0u) ? upd0(g, a0, a0S, pA, pAS)
                                                      : upd1(g, a0, a0S, pA, pAS);
                amp[rb] = (((BLOW >> rb) & 1u) == 0u) ? upd0(g, a1, a1S, pB, pBS)
                                                      : upd1(g, a1, a1S, pB, pBS);
            }
        }
    }
}

template <int G>
struct GLoop {
    static __device__ __forceinline__ void run(u64 (&amp)[32], int lane,
                                               float2 A0, float2 B0,
                                               float2 A1, float2 B1) {
        apply_gate<G>(amp, lane, A0, B0, A1, B1);
        GLoop<G + 1>::run(amp, lane, A0, B0, A1, B1);
    }
};
template <>
struct GLoop<40> {
    static __device__ __forceinline__ void run(u64 (&)[32], int,
                                               float2, float2, float2, float2) {}
};

// ---------------- measurement: <Z_q> with final transform T_4 ----------------
template <int Q>
struct MLoop {
    static __device__ __forceinline__ void run(const float (&pr)[32], int lane,
                                               float* __restrict__ outp) {
        constexpr unsigned fm  = t_row(4, Q);
        constexpr unsigned rml = fm & 31u, rmh = fm >> 5;
        constexpr unsigned BL  = blow_map(rml);
        float s = 0.f;
        #pragma unroll
        for (int r = 0; r < 32; r++)
            s += (((BL >> r) & 1u) ? -pr[r] : pr[r]);
        if (__popc(lane & (int)rmh) & 1) s = -s;
        #pragma unroll
        for (int off = 16; off; off >>= 1)
            s += __shfl_xor_sync(FULLM, s, off);
        if (lane == 0) outp[Q] = s;
        MLoop<Q + 1>::run(pr, lane, outp);
    }
};
template <>
struct MLoop<10> {
    static __device__ __forceinline__ void run(const float (&)[32], int, float*) {}
};

// compute (alpha, beta) for one gate from its angle trig + weight trig
__device__ __forceinline__ void gate_coeffs(float ca, float sa, float4 wt,
                                            float2& al, float2& be) {
    float cw = wt.x, sw = wt.y, cph = wt.z, sph = wt.w;
    float A = cw * ca, B = sw * sa, C = sw * ca, D = cw * sa;
    al = make_float2((A - B) * cph, -(A + B) * sph);
    be = make_float2((C + D) * cph,  (D - C) * sph);
}

// ---------------- main kernel ------------------------------------------------
__global__ void __launch_bounds__(128, 3)
qsim_kernel(const float* __restrict__ x, float* __restrict__ out, int B) {
    const int lane = threadIdx.x & 31;
    const int b = blockIdx.x * (blockDim.x >> 5) + (threadIdx.x >> 5);
    if (b >= B) return;

    const float* xb = x + (size_t)b * 40;
    const float PI_F = 3.14159265358979f;

    // ---- per-gate coefficients: lane g owns gate g (set0) and gate 32+g (set1)
    float ca0, sa0;
    __sincosf(0.5f * PI_F * atanf(xb[lane]), &sa0, &ca0);
    float2 A0, B0;
    gate_coeffs(ca0, sa0, g_wtab[lane], A0, B0);

    float2 A1 = make_float2(1.f, 0.f), B1 = make_float2(0.f, 0.f);
    if (lane < 8) {
        float ca1, sa1;
        __sincosf(0.5f * PI_F * atanf(xb[32 + lane]), &sa1, &ca1);
        gate_coeffs(ca1, sa1, g_wtab[32 + lane], A1, B1);
    }

    // ---- layer 0 shortcut: product state amp[p] = prod_q u_q[bit_q(p)] ----
    u64 amp[32];
    {
        // lane factor over qubits 5..9 (selected by lane bits)
        float2 sel;
        {
            float ux = __shfl_sync(FULLM, A0.x, 5), uy = __shfl_sync(FULLM, A0.y, 5);
            float wx = __shfl_sync(FULLM, B0.x, 5), wy = __shfl_sync(FULLM, B0.y, 5);
            sel = (lane & 1) ? make_float2(wx, wy) : make_float2(ux, uy);
        }
        u64 Fz = pack2(sel.x, sel.y);
        #pragma unroll
        for (int j = 1; j < 5; j++) {
            const int src = 5 + j;
            float ux = __shfl_sync(FULLM, A0.x, src), uy = __shfl_sync(FULLM, A0.y, src);
            float wx = __shfl_sync(FULLM, B0.x, src), wy = __shfl_sync(FULLM, B0.y, src);
            float sx = ((lane >> j) & 1) ? wx : ux;
            float sy = ((lane >> j) & 1) ? wy : uy;
            // Fz *= (sx + i sy)
            Fz = fma2(pack2(sx, sx), Fz, mul2(pack2(-sy, sy), swp(Fz)));
        }
        amp[0] = Fz;
        // register doubling over qubits 0..4
        #pragma unroll
        for (int q = 0; q < 5; q++) {
            float u0x = __shfl_sync(FULLM, A0.x, q), u0y = __shfl_sync(FULLM, A0.y, q);
            float u1x = __shfl_sync(FULLM, B0.x, q), u1y = __shfl_sync(FULLM, B0.y, q);
            u64 v0x = pack2(u0x, u0x), v0y = pack2(-u0y, u0y);
            u64 v1x = pack2(u1x, u1x), v1y = pack2(-u1y, u1y);
            #pragma unroll
            for (int r = 0; r < 32; r++) {
                if (r < (1 << q)) {
                    u64 z = amp[r], zS = swp(z);
                    amp[r | (1 << q)] = fma2(v1x, z, mul2(v1y, zS));
                    amp[r]            = fma2(v0x, z, mul2(v0y, zS));
                }
            }
        }
    }

    // ---- layers 1..3 (gates 10..39) ----
    GLoop<10>::run(amp, lane, A0, B0, A1, B1);

    // ---- probabilities + <Z_q> ----
    float pr[32];
    #pragma unroll
    for (int r = 0; r < 32; r++) {
        float re, im;
        unpack2(amp[r], re, im);
        pr[r] = fmaf(re, re, im * im);
    }

    MLoop<0>::run(pr, lane, out + (size_t)b * 10);
}

// ---------------- launch -----------------------------------------------------
extern "C" void kernel_launch(void* const* d_in, const int* in_sizes, int n_in,
                              void* d_out, int out_size) {
    const float* x = (const float*)d_in[0];   // [B, 40] fp32
    const float* w = (const float*)d_in[1];   // [4, 10, 2] fp32
    float* out = (float*)d_out;               // [B, 10] fp32

    int B = in_sizes[0] / 40;
    prep_kernel<<<1, 64>>>(w);
    const int THREADS = 128;
    int wpb = THREADS / 32;
    int blocks = (B + wpb - 1) / wpb;
    qsim_kernel<<<blocks, THREADS>>>(x, out, B);
}

// round 9
// speedup vs baseline: 2.0860x; 1.2476x over previous
#include <cuda_runtime.h>
#include <cuda_bf16.h>
#include <cstdint>

// ============================================================================
// ReuploadingQuantumLayer: 10-qubit statevector sim, 4 layers, B=16384.
// One warp per batch element. Split-component packed layout:
//   RE[16], IM[16] f32x2 regs/lane; pack k holds amplitudes (k,slot0),(k,slot1)
//   where slot = bit PBIT of the 5 low basis bits (PBIT chosen at compile time
//   to minimize slot-crossing gates).
// CNOT rings tracked as compile-time GF(2) basis transform (never applied).
// Layer 0 exploits |0..0>: direct product-state construction.
// All arithmetic via Blackwell packed fma.rn.f32x2 — no re/im swaps needed.
// ============================================================================

#define FULLM 0xFFFFFFFFu
typedef unsigned long long u64;

// ---------------- compile-time GF(2) linear algebra (10x10 bit matrices) ----
struct M10 { unsigned r[10]; };

__host__ __device__ constexpr M10 midentity() {
    M10 m{{0,0,0,0,0,0,0,0,0,0}};
    for (int i = 0; i < 10; i++) m.r[i] = 1u << i;
    return m;
}
__host__ __device__ constexpr M10 mmul(M10 a, M10 b) {
    M10 c{{0,0,0,0,0,0,0,0,0,0}};
    for (int i = 0; i < 10; i++) {
        unsigned v = 0;
        for (int j = 0; j < 10; j++)
            if ((a.r[i] >> j) & 1u) v ^= b.r[j];
        c.r[i] = v;
    }
    return c;
}
__host__ __device__ constexpr M10 mcnot(int c, int t) {
    M10 m = midentity();
    m.r[t] ^= (1u << c);
    return m;
}
__host__ __device__ constexpr M10 rmat() {
    M10 p = mcnot(0, 1);
    for (int c = 1; c < 10; c++) p = mmul(p, mcnot(c, (c + 1) % 10));
    return p;
}
__host__ __device__ constexpr M10 rinvmat() {
    M10 p = mcnot(9, 0);
    for (int c = 8; c >= 0; c--) p = mmul(p, mcnot(c, c + 1));
    return p;
}
// Invariant: stored[p] = true[T_l p],  T_l = (R^-1)^l,  Tinv_l = R^l
__host__ __device__ constexpr M10 tmat(int l) {
    M10 t = midentity();
    for (int k = 0; k < l; k++) t = mmul(rinvmat(), t);
    return t;
}
__host__ __device__ constexpr M10 tinvmat(int l) {
    M10 t = midentity();
    for (int k = 0; k < l; k++) t = mmul(t, rmat());
    return t;
}
__host__ __device__ constexpr unsigned t_row(int l, int q) { return tmat(l).r[q]; }
__host__ __device__ constexpr unsigned tinv_col(int l, int q) {
    M10 ti = tinvmat(l);
    unsigned v = 0;
    for (int i = 0; i < 10; i++) v |= ((ti.r[i] >> q) & 1u) << i;
    return v;
}
__host__ __device__ constexpr unsigned parity_(unsigned x) {
    x ^= x >> 16; x ^= x >> 8; x ^= x >> 4; x ^= x >> 2; x ^= x >> 1;
    return x & 1u;
}

// ---- pack-bit selection: the low bit appearing in the FEWEST gate masks ----
__host__ __device__ constexpr int count_pbit(int p) {
    int c = 0;
    for (int g = 10; g < 40; g++)
        if ((tinv_col(g / 10, g % 10) >> p) & 1u) c++;
    return c;
}
__host__ __device__ constexpr int best_pbit() {
    int bp = 0, bc = 1000;
    for (int p = 0; p < 5; p++) {
        int c = count_pbit(p);
        if (c < bc) { bc = c; bp = p; }
    }
    return bp;
}
constexpr int PBIT = best_pbit();

// remove bit P from a 5-bit mask -> 4-bit mask
__host__ __device__ constexpr unsigned compact5(unsigned m, int P) {
    return (m & ((1u << P) - 1u)) | (((m >> (P + 1)) & 31u) << P);
}
// 16-entry parity bitmap: bit k = parity(k & rmK)
__host__ __device__ constexpr unsigned blow16(unsigned rmK) {
    unsigned r = 0;
    for (unsigned k = 0; k < 16; k++) r |= parity_(k & rmK) << k;
    return r;
}

// ---------------- weight-derived trig table (batch independent) -------------
__device__ float4 g_wtab[40];   // per gate: (cos w1/2, sin w1/2, cos w0/2, sin w0/2)

__global__ void prep_kernel(const float* __restrict__ w) {
    int g = threadIdx.x;
    if (g < 40) {
        float w0 = w[2 * g + 0];
        float w1 = w[2 * g + 1];
        float4 t;
        t.x = cosf(0.5f * w1);
        t.y = sinf(0.5f * w1);
        t.z = cosf(0.5f * w0);
        t.w = sinf(0.5f * w0);
        g_wtab[g] = t;
    }
}

// ---------------- packed f32x2 primitives ------------------------------------
__device__ __forceinline__ u64 pack2(float lo, float hi) {
    u64 r;
    asm("mov.b64 %0, {%1, %2};" : "=l"(r) : "f"(lo), "f"(hi));
    return r;
}
__device__ __forceinline__ void unpack2(u64 v, float& lo, float& hi) {
    asm("mov.b64 {%0, %1}, %2;" : "=f"(lo), "=f"(hi) : "l"(v));
}
__device__ __forceinline__ u64 swp(u64 v) {   // (lo,hi) -> (hi,lo)
    float lo, hi;
    unpack2(v, lo, hi);
    return pack2(hi, lo);
}
__device__ __forceinline__ u64 fma2(u64 a, u64 b, u64 c) {
    u64 d;
    asm("fma.rn.f32x2 %0, %1, %2, %3;" : "=l"(d) : "l"(a), "l"(b), "l"(c));
    return d;
}
__device__ __forceinline__ u64 mul2(u64 a, u64 b) {
    u64 d;
    asm("mul.rn.f32x2 %0, %1, %2;" : "=l"(d) : "l"(a), "l"(b));
    return d;
}
__device__ __forceinline__ u64 add2(u64 a, u64 b) {
    u64 d;
    asm("add.rn.f32x2 %0, %1, %2;" : "=l"(d) : "l"(a), "l"(b));
    return d;
}
__device__ __forceinline__ u64 shx64(u64 v, int m) {
    return __shfl_xor_sync(FULLM, v, m);
}

// element update, side bit t (compile-time after unroll):
//   RE' = alx*REa - tau*aly*IMa - tau*bex*REb - bey*IMb
//   IM' = alx*IMa + tau*aly*REa - tau*bex*IMb + bey*REb
// TAY0/TAY1 = +/- tau-packed aly; TBX0/TBX1 = +/- tau-packed bex.
#define UPD(t, REa, IMa, REb, IMb, REo, IMo) do {                               \
    u64 _tay  = (t) ? TAY1 : TAY0;                                              \
    u64 _ntay = (t) ? TAY0 : TAY1;                                              \
    u64 _ntbx = (t) ? TBX0 : TBX1;                                              \
    u64 _ro = fma2(ALX, (REa), fma2(_ntay, (IMa), fma2(_ntbx, (REb), mul2(NBEY, (IMb))))); \
    u64 _io = fma2(ALX, (IMa), fma2(_tay,  (REa), fma2(_ntbx, (IMb), mul2(BEY,  (REb))))); \
    (REo) = _ro; (IMo) = _io; } while (0)

// ---------------- one gate (fully unrolled, masks are immediates) ------------
template <int G>
__device__ __forceinline__ void apply_gate(u64 (&RE)[16], u64 (&IM)[16], int lane,
                                           float2 A0, float2 B0,
                                           float2 A1, float2 B1) {
    constexpr unsigned rm    = t_row(G / 10, G % 10);
    constexpr unsigned v     = tinv_col(G / 10, G % 10);
    constexpr unsigned vlow  = v & 31u,  vhigh = v >> 5;
    constexpr unsigned rml   = rm & 31u, rmh   = rm >> 5;
    constexpr unsigned vP    = (vlow >> PBIT) & 1u;
    constexpr unsigned vK    = compact5(vlow, PBIT);
    constexpr unsigned rmP   = (rml >> PBIT) & 1u;
    constexpr unsigned rmK   = compact5(rml, PBIT);
    constexpr unsigned PARK  = blow16(rmK);
    constexpr int src = G & 31;

    // broadcast alpha, beta (computed by owner lane)
    float alx = __shfl_sync(FULLM, (G < 32) ? A0.x : A1.x, src);
    float aly = __shfl_sync(FULLM, (G < 32) ? A0.y : A1.y, src);
    float bex = __shfl_sync(FULLM, (G < 32) ? B0.x : B1.x, src);
    float bey = __shfl_sync(FULLM, (G < 32) ? B0.y : B1.y, src);

    bool blane = (__popc(lane & (int)rmh) & 1) != 0;
    float e  = blane ? -1.f : 1.f;
    float ey = e * aly, ex = e * bex;
    float sy = rmP ? -ey : ey;      // hi-slot sign factor
    float sx = rmP ? -ex : ex;

    u64 ALX  = pack2(alx, alx);
    u64 BEY  = pack2(bey, bey);
    u64 NBEY = pack2(-bey, -bey);
    u64 TAY0 = pack2(ey, sy),  TAY1 = pack2(-ey, -sy);
    u64 TBX0 = pack2(ex, sx),  TBX1 = pack2(-ex, -sx);

    if (vhigh == 0u) {
        if (vK == 0u) {
            // vP==1: partner is the other slot of the same pack
            #pragma unroll
            for (int k = 0; k < 16; k++) {
                u64 ra = RE[k], ia = IM[k];
                u64 rb = swp(ra), ib = swp(ia);
                UPD((PARK >> k) & 1u, ra, ia, rb, ib, RE[k], IM[k]);
            }
        } else {
            constexpr unsigned hb = vK & (0u - vK);
            #pragma unroll
            for (int k = 0; k < 16; k++) {
                if ((k & (int)hb) == 0) {
                    const int kb = k ^ (int)vK;
                    u64 ra = RE[k],  ia = IM[k];
                    u64 rb = RE[kb], ib = IM[kb];
                    u64 rbS = vP ? swp(rb) : rb, ibS = vP ? swp(ib) : ib;
                    u64 raS = vP ? swp(ra) : ra, iaS = vP ? swp(ia) : ia;
                    UPD((PARK >> k)  & 1u, ra, ia, rbS, ibS, RE[k],  IM[k]);
                    UPD((PARK >> kb) & 1u, rb, ib, raS, iaS, RE[kb], IM[kb]);
                }
            }
        }
    } else {
        if (vK == 0u) {
            #pragma unroll
            for (int k = 0; k < 16; k++) {
                u64 pr = shx64(RE[k], (int)vhigh);
                u64 pi = shx64(IM[k], (int)vhigh);
                if (vP) { pr = swp(pr); pi = swp(pi); }
                u64 ra = RE[k], ia = IM[k];
                UPD((PARK >> k) & 1u, ra, ia, pr, pi, RE[k], IM[k]);
            }
        } else {
            // pair-lockstep: all shuffles of a pair read pre-update values
            constexpr unsigned hb = vK & (0u - vK);
            #pragma unroll
            for (int k = 0; k < 16; k++) {
                if ((k & (int)hb) == 0) {
                    const int kb = k ^ (int)vK;
                    u64 pAr = shx64(RE[kb], (int)vhigh);
                    u64 pAi = shx64(IM[kb], (int)vhigh);
                    u64 pBr = shx64(RE[k],  (int)vhigh);
                    u64 pBi = shx64(IM[k],  (int)vhigh);
                    if (vP) { pAr = swp(pAr); pAi = swp(pAi);
                              pBr = swp(pBr); pBi = swp(pBi); }
                    u64 ra = RE[k], ia = IM[k], rb = RE[kb], ib = IM[kb];
                    UPD((PARK >> k)  & 1u, ra, ia, pAr, pAi, RE[k],  IM[k]);
                    UPD((PARK >> kb) & 1u, rb, ib, pBr, pBi, RE[kb], IM[kb]);
                }
            }
        }
    }
}

template <int G>
struct GLoop {
    static __device__ __forceinline__ void run(u64 (&RE)[16], u64 (&IM)[16], int lane,
                                               float2 A0, float2 B0,
                                               float2 A1, float2 B1) {
        apply_gate<G>(RE, IM, lane, A0, B0, A1, B1);
        GLoop<G + 1>::run(RE, IM, lane, A0, B0, A1, B1);
    }
};
template <>
struct GLoop<40> {
    static __device__ __forceinline__ void run(u64 (&)[16], u64 (&)[16], int,
                                               float2, float2, float2, float2) {}
};

// ---------------- measurement: <Z_q> with final transform T_4 ----------------
template <int Q>
__device__ __forceinline__ float zsum(const u64 (&pr2)[16], int lane) {
    constexpr unsigned fm   = t_row(4, Q);
    constexpr unsigned rml  = fm & 31u, rmh = fm >> 5;
    constexpr unsigned rmP  = (rml >> PBIT) & 1u;
    constexpr unsigned rmK  = compact5(rml, PBIT);
    constexpr unsigned PARK = blow16(rmK);
    const u64 SGNp = pack2(1.f,  rmP ? -1.f :  1.f);
    const u64 SGNm = pack2(-1.f, rmP ?  1.f : -1.f);
    u64 acc0 = 0ull, acc1 = 0ull;
    #pragma unroll
    for (int k = 0; k < 8; k++)
        acc0 = fma2(pr2[k], ((PARK >> k) & 1u) ? SGNm : SGNp, acc0);
    #pragma unroll
    for (int k = 8; k < 16; k++)
        acc1 = fma2(pr2[k], ((PARK >> k) & 1u) ? SGNm : SGNp, acc1);
    float lo, hi;
    unpack2(add2(acc0, acc1), lo, hi);
    float s = lo + hi;
    if (__popc(lane & (int)rmh) & 1) s = -s;
    return s;
}

template <int Q>   // processes Q and Q+1 together (Q even)
struct M2 {
    static __device__ __forceinline__ void run(const u64 (&pr2)[16], int lane,
                                               float* __restrict__ outp) {
        float sA = zsum<Q>(pr2, lane);
        float sB = zsum<Q + 1>(pr2, lane);
        u64 v = pack2(sA, sB);
        #pragma unroll
        for (int off = 16; off; off >>= 1)
            v = add2(v, shx64(v, off));
        if (lane == 0)
            *reinterpret_cast<u64*>(outp + Q) = v;   // (b*10+Q)*4 is 8B-aligned
        M2<Q + 2>::run(pr2, lane, outp);
    }
};
template <>
struct M2<10> {
    static __device__ __forceinline__ void run(const u64 (&)[16], int, float*) {}
};

// compute (alpha, beta) for one gate from its angle trig + weight trig
__device__ __forceinline__ void gate_coeffs(float ca, float sa, float4 wt,
                                            float2& al, float2& be) {
    float cw = wt.x, sw = wt.y, cph = wt.z, sph = wt.w;
    float A = cw * ca, B = sw * sa, C = sw * ca, D = cw * sa;
    al = make_float2((A - B) * cph, -(A + B) * sph);
    be = make_float2((C + D) * cph,  (D - C) * sph);
}

// ---------------- main kernel ------------------------------------------------
__global__ void __launch_bounds__(128, 4)
qsim_kernel(const float* __restrict__ x, float* __restrict__ out, int B) {
    const int lane = threadIdx.x & 31;
    const int b = blockIdx.x * (blockDim.x >> 5) + (threadIdx.x >> 5);
    if (b >= B) return;

    const float* xb = x + (size_t)b * 40;
    const float PI_F = 3.14159265358979f;

    // ---- per-gate coefficients: lane g owns gate g (set0) and gate 32+g (set1)
    float ca0, sa0;
    __sincosf(0.5f * PI_F * atanf(xb[lane]), &sa0, &ca0);
    float2 A0, B0;
    gate_coeffs(ca0, sa0, g_wtab[lane], A0, B0);

    float2 A1 = make_float2(1.f, 0.f), B1 = make_float2(0.f, 0.f);
    if (lane < 8) {
        float ca1, sa1;
        __sincosf(0.5f * PI_F * atanf(xb[32 + lane]), &sa1, &ca1);
        gate_coeffs(ca1, sa1, g_wtab[32 + lane], A1, B1);
    }

    // ---- layer 0: product state, built directly in split layout ----
    // lane factor over qubits 5..9 (selected by lane bits), scalar complex
    float fzr, fzi;
    {
        float ux = __shfl_sync(FULLM, A0.x, 5), uy = __shfl_sync(FULLM, A0.y, 5);
        float wx = __shfl_sync(FULLM, B0.x, 5), wy = __shfl_sync(FULLM, B0.y, 5);
        fzr = (lane & 1) ? wx : ux;
        fzi = (lane & 1) ? wy : uy;
        #pragma unroll
        for (int j = 1; j < 5; j++) {
            const int srcl = 5 + j;
            float ax = __shfl_sync(FULLM, A0.x, srcl), ay = __shfl_sync(FULLM, A0.y, srcl);
            float bx = __shfl_sync(FULLM, B0.x, srcl), by = __shfl_sync(FULLM, B0.y, srcl);
            float cx = ((lane >> j) & 1) ? bx : ax;
            float cy = ((lane >> j) & 1) ? by : ay;
            float nr = fzr * cx - fzi * cy;
            float ni = fzr * cy + fzi * cx;
            fzr = nr; fzi = ni;
        }
    }

    u64 RE[16], IM[16];
    // slot qubit = PBIT
    {
        float ax = __shfl_sync(FULLM, A0.x, PBIT), ay = __shfl_sync(FULLM, A0.y, PBIT);
        float bx = __shfl_sync(FULLM, B0.x, PBIT), by = __shfl_sync(FULLM, B0.y, PBIT);
        RE[0] = pack2(fzr * ax - fzi * ay, fzr * bx - fzi * by);
        IM[0] = pack2(fzr * ay + fzi * ax, fzr * by + fzi * bx);
    }
    // pack-bit doubling over remaining low qubits
    #pragma unroll
    for (int j = 0; j < 4; j++) {
        const int q = (j < PBIT) ? j : j + 1;
        float u0x = __shfl_sync(FULLM, A0.x, q), u0y = __shfl_sync(FULLM, A0.y, q);
        float u1x = __shfl_sync(FULLM, B0.x, q), u1y = __shfl_sync(FULLM, B0.y, q);
        u64 U0X = pack2(u0x, u0x), U0Y = pack2(u0y, u0y), NU0Y = pack2(-u0y, -u0y);
        u64 U1X = pack2(u1x, u1x), U1Y = pack2(u1y, u1y), NU1Y = pack2(-u1y, -u1y);
        #pragma unroll
        for (int k = 0; k < 16; k++) {
            if (k < (1 << j)) {
                u64 rr = RE[k], ii = IM[k];
                RE[k | (1 << j)] = fma2(U1X, rr, mul2(NU1Y, ii));
                IM[k | (1 << j)] = fma2(U1X, ii, mul2(U1Y,  rr));
                RE[k]            = fma2(U0X, rr, mul2(NU0Y, ii));
                IM[k]            = fma2(U0X, ii, mul2(U0Y,  rr));
            }
        }
    }

    // ---- layers 1..3 (gates 10..39) ----
    GLoop<10>::run(RE, IM, lane, A0, B0, A1, B1);

    // ---- probabilities (packed) + <Z_q> ----
    u64 pr2[16];
    #pragma unroll
    for (int k = 0; k < 16; k++)
        pr2[k] = fma2(RE[k], RE[k], mul2(IM[k], IM[k]));

    M2<0>::run(pr2, lane, out + (size_t)b * 10);
}

// ---------------- launch -----------------------------------------------------
extern "C" void kernel_launch(void* const* d_in, const int* in_sizes, int n_in,
                              void* d_out, int out_size) {
    const float* x = (const float*)d_in[0];   // [B, 40] fp32
    const float* w = (const float*)d_in[1];   // [4, 10, 2] fp32
    float* out = (float*)d_out;               // [B, 10] fp32

    int B = in_sizes[0] / 40;
    prep_kernel<<<1, 64>>>(w);
    const int THREADS = 128;
    int wpb = THREADS / 32;
    int blocks = (B + wpb - 1) / wpb;
    qsim_kernel<<<blocks, THREADS>>>(x, out, B);
}